// round 1
// baseline (speedup 1.0000x reference)
#include <cuda_runtime.h>
#include <cuda_bf16.h>

// ---------------------------------------------------------------------------
// ModelSimple: conv4d(1->5,k7) + ReLU -> conv4d(5->10,k7) + ReLU -> Linear -> sigmoid
// x: [128,1,18,18,18,18] f32 -> h1: [128,5,12^4] -> h2: [128,10,6^4] -> out [128,1]
// Strategy: CUDA-core baseline using packed f32x2 FMA (SASS FFMA2) for 2x fp32 rate.
// ---------------------------------------------------------------------------

#define ULL unsigned long long

__device__ __forceinline__ ULL pack2(float a, float b) {
    ULL r;
    asm("mov.b64 %0, {%1, %2};" : "=l"(r) : "f"(a), "f"(b));
    return r;
}
__device__ __forceinline__ ULL fma2(ULL a, ULL b, ULL c) {
    ULL d;
    asm("fma.rn.f32x2 %0, %1, %2, %3;" : "=l"(d) : "l"(a), "l"(b), "l"(c));
    return d;
}
__device__ __forceinline__ float2 unpack2(ULL v) {
    float2 f;
    asm("mov.b64 {%0, %1}, %2;" : "=f"(f.x), "=f"(f.y) : "l"(v));
    return f;
}

// Scratch (device globals: allocation-free per harness rules)
__device__ float g_h1[128 * 5 * 20736];   // [b][oc][oh*1728 + ow*144 + od*12 + ot]
__device__ float g_h2[128 * 10 * 1296];   // [b][oc][oh*216 + ow*36 + od*6 + ot]

// ---------------------------------------------------------------------------
// Kernel 1: conv1 (1->5 ch, k=7) + bias + ReLU
// grid = 128*12 blocks (b, oh); 288 threads = (ow[12], od[12], ot_half[2])
// SMEM: x slab [7,18,18,18] = 40824 f + w1 12005 f = 211,316 B dynamic
// ---------------------------------------------------------------------------
__global__ __launch_bounds__(288, 1)
void conv1_kernel(const float* __restrict__ x,
                  const float* __restrict__ w1,
                  const float* __restrict__ b1) {
    extern __shared__ float sm[];
    float* sx = sm;           // 40824 floats
    float* sw = sm + 40824;   // 12005 floats

    const int bx  = blockIdx.x;
    const int b   = bx / 12;
    const int oh  = bx % 12;
    const int tid = threadIdx.x;

    // Cooperative loads: x slab is one contiguous chunk (h outermost spatial dim)
    {
        const float4* s4 = (const float4*)(x + b * 104976 + oh * 5832);
        float4* d4 = (float4*)sx;
        for (int i = tid; i < 10206; i += 288) d4[i] = s4[i];
        for (int i = tid; i < 12005; i += 288) sw[i] = w1[i];
    }
    __syncthreads();

    const int ow  = tid / 24;
    const int r   = tid % 24;
    const int od  = r >> 1;
    const int ot0 = (r & 1) * 6;   // ot in [ot0, ot0+6)

    ULL acc[5][3];
    #pragma unroll
    for (int oc = 0; oc < 5; oc++)
        #pragma unroll
        for (int p = 0; p < 3; p++) acc[oc][p] = 0ULL;

    const int colbase = od * 18 + ot0;

    #pragma unroll 1
    for (int kh = 0; kh < 7; kh++) {
        #pragma unroll 1
        for (int kw = 0; kw < 7; kw++) {
            const float* rowc = sx + kh * 5832 + (ow + kw) * 324 + colbase;
            #pragma unroll 1
            for (int kd = 0; kd < 7; kd++) {
                const float* row = rowc + kd * 18;
                // Register-resident x row (12 contiguous floats, 8B aligned)
                float xr[12];
                #pragma unroll
                for (int i = 0; i < 6; i++) {
                    float2 v = *(const float2*)(row + 2 * i);
                    xr[2 * i] = v.x; xr[2 * i + 1] = v.y;
                }
                // All 11 adjacent pairs, built once, reused across kt/oc
                ULL xp[11];
                #pragma unroll
                for (int j = 0; j < 11; j++) xp[j] = pack2(xr[j], xr[j + 1]);

                const int kbase = ((kh * 7 + kw) * 7 + kd) * 7;
                #pragma unroll
                for (int kt = 0; kt < 7; kt++) {
                    #pragma unroll
                    for (int oc = 0; oc < 5; oc++) {
                        const float wv = sw[oc * 2401 + kbase + kt]; // SMEM broadcast
                        const ULL wp = pack2(wv, wv);
                        acc[oc][0] = fma2(xp[kt + 0], wp, acc[oc][0]);
                        acc[oc][1] = fma2(xp[kt + 2], wp, acc[oc][1]);
                        acc[oc][2] = fma2(xp[kt + 4], wp, acc[oc][2]);
                    }
                }
            }
        }
    }

    // bias + ReLU + store (float2 aligned)
    const int sbase = oh * 1728 + ow * 144 + od * 12 + ot0;
    #pragma unroll
    for (int oc = 0; oc < 5; oc++) {
        const float bb = __ldg(b1 + oc);
        float* dst = g_h1 + (size_t)(b * 5 + oc) * 20736 + sbase;
        #pragma unroll
        for (int p = 0; p < 3; p++) {
            float2 a = unpack2(acc[oc][p]);
            float2 o;
            o.x = fmaxf(a.x + bb, 0.0f);
            o.y = fmaxf(a.y + bb, 0.0f);
            *(float2*)(dst + 2 * p) = o;
        }
    }
}

// ---------------------------------------------------------------------------
// Kernel 2: conv2 (5->10 ch, k=7) + bias + ReLU
// grid = 128 blocks (b); 256 threads; 216 active = (oh[6], ow[6], od[6]) strips
// Loop over ic: SMEM h1 slab [12^4]=20736 f + w2 slice [10][2401]=24010 f = 178,984 B
// ---------------------------------------------------------------------------
__global__ __launch_bounds__(256, 1)
void conv2_kernel(const float* __restrict__ w2,
                  const float* __restrict__ b2) {
    extern __shared__ float sm[];
    float* sx = sm;           // 20736 floats
    float* sw = sm + 20736;   // 24010 floats

    const int b   = blockIdx.x;
    const int tid = threadIdx.x;
    const int s   = (tid < 216) ? tid : 215;   // clamp; inactive threads compute redundantly
    const int oh  = s / 36;
    const int ow  = (s % 36) / 6;
    const int od  = s % 6;

    ULL acc[10][3];
    #pragma unroll
    for (int oc = 0; oc < 10; oc++)
        #pragma unroll
        for (int p = 0; p < 3; p++) acc[oc][p] = 0ULL;

    for (int ic = 0; ic < 5; ic++) {
        __syncthreads();   // protect previous iteration's SMEM reads
        {
            const float4* s4 = (const float4*)(g_h1 + (size_t)(b * 5 + ic) * 20736);
            float4* d4 = (float4*)sx;
            for (int i = tid; i < 5184; i += 256) d4[i] = s4[i];
            #pragma unroll 1
            for (int oc = 0; oc < 10; oc++) {
                const float* wsrc = w2 + (size_t)(oc * 5 + ic) * 2401;
                for (int i = tid; i < 2401; i += 256) sw[oc * 2401 + i] = wsrc[i];
            }
        }
        __syncthreads();

        #pragma unroll 1
        for (int kh = 0; kh < 7; kh++) {
            #pragma unroll 1
            for (int kw = 0; kw < 7; kw++) {
                const float* rowc = sx + ((oh + kh) * 12 + ow + kw) * 144 + od * 12;
                #pragma unroll 1
                for (int kd = 0; kd < 7; kd++) {
                    const float* row = rowc + kd * 12;
                    float xr[12];
                    #pragma unroll
                    for (int i = 0; i < 6; i++) {
                        float2 v = *(const float2*)(row + 2 * i);
                        xr[2 * i] = v.x; xr[2 * i + 1] = v.y;
                    }
                    ULL xp[11];
                    #pragma unroll
                    for (int j = 0; j < 11; j++) xp[j] = pack2(xr[j], xr[j + 1]);

                    const int kbase = ((kh * 7 + kw) * 7 + kd) * 7;
                    #pragma unroll
                    for (int kt = 0; kt < 7; kt++) {
                        #pragma unroll
                        for (int oc = 0; oc < 10; oc++) {
                            const float wv = sw[oc * 2401 + kbase + kt];
                            const ULL wp = pack2(wv, wv);
                            acc[oc][0] = fma2(xp[kt + 0], wp, acc[oc][0]);
                            acc[oc][1] = fma2(xp[kt + 2], wp, acc[oc][1]);
                            acc[oc][2] = fma2(xp[kt + 4], wp, acc[oc][2]);
                        }
                    }
                }
            }
        }
    }

    if (tid < 216) {
        const int sp = oh * 216 + ow * 36 + od * 6;
        #pragma unroll
        for (int oc = 0; oc < 10; oc++) {
            const float bb = __ldg(b2 + oc);
            float* dst = g_h2 + (size_t)(b * 10 + oc) * 1296 + sp;
            #pragma unroll
            for (int p = 0; p < 3; p++) {
                float2 a = unpack2(acc[oc][p]);
                float2 o;
                o.x = fmaxf(a.x + bb, 0.0f);
                o.y = fmaxf(a.y + bb, 0.0f);
                *(float2*)(dst + 2 * p) = o;
            }
        }
    }
}

// ---------------------------------------------------------------------------
// Kernel 3: Linear(12960 -> 1) + sigmoid. grid = 128 blocks (b), 128 threads.
// ---------------------------------------------------------------------------
__global__ __launch_bounds__(128, 8)
void head_kernel(const float* __restrict__ wl,
                 const float* __restrict__ bl,
                 float* __restrict__ out) {
    const int b   = blockIdx.x;
    const int tid = threadIdx.x;
    const float* h = g_h2 + (size_t)b * 12960;

    float sum = 0.0f;
    for (int i = tid; i < 12960; i += 128)
        sum += h[i] * wl[i];

    #pragma unroll
    for (int o = 16; o > 0; o >>= 1)
        sum += __shfl_xor_sync(0xffffffffu, sum, o);

    __shared__ float red[4];
    if ((tid & 31) == 0) red[tid >> 5] = sum;
    __syncthreads();
    if (tid == 0) {
        float z = red[0] + red[1] + red[2] + red[3] + bl[0];
        out[b] = 1.0f / (1.0f + expf(-z));
    }
}

// ---------------------------------------------------------------------------
extern "C" void kernel_launch(void* const* d_in, const int* in_sizes, int n_in,
                              void* d_out, int out_size) {
    const float* x  = (const float*)d_in[0];
    const float* w1 = (const float*)d_in[1];
    const float* b1 = (const float*)d_in[2];
    const float* w2 = (const float*)d_in[3];
    const float* b2 = (const float*)d_in[4];
    const float* wl = (const float*)d_in[5];
    const float* bl = (const float*)d_in[6];

    const int smem1 = 52829 * 4;  // 211,316 B
    const int smem2 = 44746 * 4;  // 178,984 B
    cudaFuncSetAttribute(conv1_kernel, cudaFuncAttributeMaxDynamicSharedMemorySize, smem1);
    cudaFuncSetAttribute(conv2_kernel, cudaFuncAttributeMaxDynamicSharedMemorySize, smem2);

    conv1_kernel<<<128 * 12, 288, smem1>>>(x, w1, b1);
    conv2_kernel<<<128, 256, smem2>>>(w2, b2);
    head_kernel<<<128, 128>>>(wl, bl, (float*)d_out);
}

// round 2
// speedup vs baseline: 1.0388x; 1.0388x over previous
#include <cuda_runtime.h>
#include <cuda_bf16.h>

// ---------------------------------------------------------------------------
// ModelSimple: conv4d(1->5,k7)+ReLU -> conv4d(5->10,k7)+ReLU -> Linear -> sigmoid
// x: [128,1,18^4] f32 -> h1: [128,5,12^4] -> h2: [128,10,6^4] -> out [128,1]
// R2: raise occupancy (conv1 split-K over kh*kw, conv2 split over oc),
//     8-padded weight SMEM for LDS.64 weight loads.
// ---------------------------------------------------------------------------

#define ULL unsigned long long

__device__ __forceinline__ ULL pack2(float a, float b) {
    ULL r;
    asm("mov.b64 %0, {%1, %2};" : "=l"(r) : "f"(a), "f"(b));
    return r;
}
__device__ __forceinline__ ULL fma2(ULL a, ULL b, ULL c) {
    ULL d;
    asm("fma.rn.f32x2 %0, %1, %2, %3;" : "=l"(d) : "l"(a), "l"(b), "l"(c));
    return d;
}
__device__ __forceinline__ float2 unpack2(ULL v) {
    float2 f;
    asm("mov.b64 {%0, %1}, %2;" : "=f"(f.x), "=f"(f.y) : "l"(v));
    return f;
}

// Scratch (device globals: allocation-free per harness rules)
__device__ float g_h1[128 * 5 * 20736];   // [b][oc][oh*1728 + ow*144 + od*12 + ot]
__device__ float g_h2[128 * 10 * 1296];   // [b][oc][oh*216 + ow*36 + od*6 + ot]

// ---------------------------------------------------------------------------
// conv1: grid = 128*12 (b, oh); 576 threads = 2 khw-groups x (ow12, od12, ot_half2)
// SMEM: x slab [7,18,18,18]=40824 f + w1 padded 5*343*8=13720 f = 218,176 B
// Group 0: khw in [0,25); group 1: khw in [25,49); SMEM reduction at the end.
// ---------------------------------------------------------------------------
__global__ __launch_bounds__(576, 1)
void conv1_kernel(const float* __restrict__ x,
                  const float* __restrict__ w1,
                  const float* __restrict__ b1) {
    extern __shared__ float sm[];
    float* sx = sm;           // 40824 floats
    float* sw = sm + 40824;   // 13720 floats (padded weights; later reused for reduction)

    const int bx  = blockIdx.x;
    const int b   = bx / 12;
    const int oh  = bx % 12;
    const int tid = threadIdx.x;

    // Stage x slab (contiguous) and padded weights
    {
        const float4* s4 = (const float4*)(x + b * 104976 + oh * 5832);
        float4* d4 = (float4*)sx;
        for (int i = tid; i < 10206; i += 576) d4[i] = s4[i];
        for (int i = tid; i < 12005; i += 576) {
            const int oc = i / 2401;
            const int r  = i - oc * 2401;
            const int ki = r / 7;
            const int kt = r - ki * 7;
            sw[(oc * 343 + ki) * 8 + kt] = w1[i];
        }
    }
    __syncthreads();

    const int g   = tid / 288;           // split-K group
    const int t   = tid - g * 288;
    const int ow  = t / 24;
    const int r   = t % 24;
    const int od  = r >> 1;
    const int ot0 = (r & 1) * 6;

    ULL acc[5][3];
    #pragma unroll
    for (int oc = 0; oc < 5; oc++)
        #pragma unroll
        for (int p = 0; p < 3; p++) acc[oc][p] = 0ULL;

    const int colbase = od * 18 + ot0;
    const int khw0 = g ? 25 : 0;
    const int khw1 = g ? 49 : 25;

    #pragma unroll 1
    for (int khw = khw0; khw < khw1; khw++) {
        const int kh = khw / 7;
        const int kw = khw - kh * 7;
        const float* rowc = sx + kh * 5832 + (ow + kw) * 324 + colbase;
        #pragma unroll 1
        for (int kd = 0; kd < 7; kd++) {
            const float* row = rowc + kd * 18;
            // 6 aligned float2 loads cover x[0..11]
            float2 v0 = *(const float2*)(row + 0);
            float2 v1 = *(const float2*)(row + 2);
            float2 v2 = *(const float2*)(row + 4);
            float2 v3 = *(const float2*)(row + 6);
            float2 v4 = *(const float2*)(row + 8);
            float2 v5 = *(const float2*)(row + 10);
            ULL xp[11];
            xp[0]  = pack2(v0.x, v0.y);
            xp[2]  = pack2(v1.x, v1.y);
            xp[4]  = pack2(v2.x, v2.y);
            xp[6]  = pack2(v3.x, v3.y);
            xp[8]  = pack2(v4.x, v4.y);
            xp[10] = pack2(v5.x, v5.y);
            xp[1]  = pack2(v0.y, v1.x);
            xp[3]  = pack2(v1.y, v2.x);
            xp[5]  = pack2(v2.y, v3.x);
            xp[7]  = pack2(v3.y, v4.x);
            xp[9]  = pack2(v4.y, v5.x);

            const int kib = khw * 7 + kd;
            #pragma unroll
            for (int oc = 0; oc < 5; oc++) {
                const float* wb = sw + (oc * 343 + kib) * 8;
                const float2 wA = *(const float2*)(wb + 0);
                const float2 wB = *(const float2*)(wb + 2);
                const float2 wC = *(const float2*)(wb + 4);
                const float2 wD = *(const float2*)(wb + 6);
                const float wk[7] = {wA.x, wA.y, wB.x, wB.y, wC.x, wC.y, wD.x};
                #pragma unroll
                for (int kt = 0; kt < 7; kt++) {
                    const ULL wp = pack2(wk[kt], wk[kt]);
                    acc[oc][0] = fma2(xp[kt + 0], wp, acc[oc][0]);
                    acc[oc][1] = fma2(xp[kt + 2], wp, acc[oc][1]);
                    acc[oc][2] = fma2(xp[kt + 4], wp, acc[oc][2]);
                }
            }
        }
    }

    // Cross-group reduction through SMEM (reuse weight region: 288*15*8B = 34.5KB <= 54.9KB)
    __syncthreads();                       // everyone done reading sw as weights
    ULL* red = (ULL*)sw;
    if (g == 1) {
        #pragma unroll
        for (int oc = 0; oc < 5; oc++)
            #pragma unroll
            for (int p = 0; p < 3; p++)
                red[t * 15 + oc * 3 + p] = acc[oc][p];
    }
    __syncthreads();

    if (g == 0) {
        const int sbase = oh * 1728 + ow * 144 + od * 12 + ot0;
        #pragma unroll
        for (int oc = 0; oc < 5; oc++) {
            const float bb = __ldg(b1 + oc);
            float* dst = g_h1 + (size_t)(b * 5 + oc) * 20736 + sbase;
            #pragma unroll
            for (int p = 0; p < 3; p++) {
                const float2 a = unpack2(acc[oc][p]);
                const float2 q = unpack2(red[t * 15 + oc * 3 + p]);
                float2 o;
                o.x = fmaxf(a.x + q.x + bb, 0.0f);
                o.y = fmaxf(a.y + q.y + bb, 0.0f);
                *(float2*)(dst + 2 * p) = o;
            }
        }
    }
}

// ---------------------------------------------------------------------------
// conv2: grid = 128 (b); 432 threads = 2 oc-groups x (oh6, ow6, od6)
// Loop ic: SMEM h1 slab 20736 f + w2 slice padded 10*343*8=27440 f = 192,704 B
// ---------------------------------------------------------------------------
__global__ __launch_bounds__(432, 1)
void conv2_kernel(const float* __restrict__ w2,
                  const float* __restrict__ b2) {
    extern __shared__ float sm[];
    float* sx = sm;           // 20736 floats
    float* sw = sm + 20736;   // 27440 floats (padded)

    const int b   = blockIdx.x;
    const int tid = threadIdx.x;
    const int ocg = tid / 216;            // 0 or 1 -> oc base 0 / 5
    const int s   = tid - ocg * 216;
    const int oh  = s / 36;
    const int ow  = (s % 36) / 6;
    const int od  = s % 6;
    const int ocb = ocg * 5;

    ULL acc[5][3];
    #pragma unroll
    for (int oc = 0; oc < 5; oc++)
        #pragma unroll
        for (int p = 0; p < 3; p++) acc[oc][p] = 0ULL;

    for (int ic = 0; ic < 5; ic++) {
        __syncthreads();   // protect previous iteration's SMEM reads
        {
            const float4* s4 = (const float4*)(g_h1 + (size_t)(b * 5 + ic) * 20736);
            float4* d4 = (float4*)sx;
            for (int i = tid; i < 5184; i += 432) d4[i] = s4[i];
            for (int i = tid; i < 24010; i += 432) {
                const int oc = i / 2401;
                const int r  = i - oc * 2401;
                const int ki = r / 7;
                const int kt = r - ki * 7;
                sw[(oc * 343 + ki) * 8 + kt] = w2[(size_t)(oc * 5 + ic) * 2401 + r];
            }
        }
        __syncthreads();

        #pragma unroll 1
        for (int khw = 0; khw < 49; khw++) {
            const int kh = khw / 7;
            const int kw = khw - kh * 7;
            const float* rowc = sx + ((oh + kh) * 12 + ow + kw) * 144 + od * 12;
            #pragma unroll 1
            for (int kd = 0; kd < 7; kd++) {
                const float* row = rowc + kd * 12;
                float2 v0 = *(const float2*)(row + 0);
                float2 v1 = *(const float2*)(row + 2);
                float2 v2 = *(const float2*)(row + 4);
                float2 v3 = *(const float2*)(row + 6);
                float2 v4 = *(const float2*)(row + 8);
                float2 v5 = *(const float2*)(row + 10);
                ULL xp[11];
                xp[0]  = pack2(v0.x, v0.y);
                xp[2]  = pack2(v1.x, v1.y);
                xp[4]  = pack2(v2.x, v2.y);
                xp[6]  = pack2(v3.x, v3.y);
                xp[8]  = pack2(v4.x, v4.y);
                xp[10] = pack2(v5.x, v5.y);
                xp[1]  = pack2(v0.y, v1.x);
                xp[3]  = pack2(v1.y, v2.x);
                xp[5]  = pack2(v2.y, v3.x);
                xp[7]  = pack2(v3.y, v4.x);
                xp[9]  = pack2(v4.y, v5.x);

                const int kib = khw * 7 + kd;
                #pragma unroll
                for (int oc = 0; oc < 5; oc++) {
                    const float* wb = sw + ((ocb + oc) * 343 + kib) * 8;
                    const float2 wA = *(const float2*)(wb + 0);
                    const float2 wB = *(const float2*)(wb + 2);
                    const float2 wC = *(const float2*)(wb + 4);
                    const float2 wD = *(const float2*)(wb + 6);
                    const float wk[7] = {wA.x, wA.y, wB.x, wB.y, wC.x, wC.y, wD.x};
                    #pragma unroll
                    for (int kt = 0; kt < 7; kt++) {
                        const ULL wp = pack2(wk[kt], wk[kt]);
                        acc[oc][0] = fma2(xp[kt + 0], wp, acc[oc][0]);
                        acc[oc][1] = fma2(xp[kt + 2], wp, acc[oc][1]);
                        acc[oc][2] = fma2(xp[kt + 4], wp, acc[oc][2]);
                    }
                }
            }
        }
    }

    {
        const int sp = oh * 216 + ow * 36 + od * 6;
        #pragma unroll
        for (int oc = 0; oc < 5; oc++) {
            const float bb = __ldg(b2 + ocb + oc);
            float* dst = g_h2 + (size_t)(b * 10 + ocb + oc) * 1296 + sp;
            #pragma unroll
            for (int p = 0; p < 3; p++) {
                const float2 a = unpack2(acc[oc][p]);
                float2 o;
                o.x = fmaxf(a.x + bb, 0.0f);
                o.y = fmaxf(a.y + bb, 0.0f);
                *(float2*)(dst + 2 * p) = o;
            }
        }
    }
}

// ---------------------------------------------------------------------------
// head: Linear(12960 -> 1) + sigmoid. grid = 128 (b), 128 threads.
// ---------------------------------------------------------------------------
__global__ __launch_bounds__(128, 8)
void head_kernel(const float* __restrict__ wl,
                 const float* __restrict__ bl,
                 float* __restrict__ out) {
    const int b   = blockIdx.x;
    const int tid = threadIdx.x;
    const float* h = g_h2 + (size_t)b * 12960;

    float sum = 0.0f;
    for (int i = tid; i < 12960; i += 128)
        sum += h[i] * wl[i];

    #pragma unroll
    for (int o = 16; o > 0; o >>= 1)
        sum += __shfl_xor_sync(0xffffffffu, sum, o);

    __shared__ float red[4];
    if ((tid & 31) == 0) red[tid >> 5] = sum;
    __syncthreads();
    if (tid == 0) {
        float z = red[0] + red[1] + red[2] + red[3] + bl[0];
        out[b] = 1.0f / (1.0f + expf(-z));
    }
}

// ---------------------------------------------------------------------------
extern "C" void kernel_launch(void* const* d_in, const int* in_sizes, int n_in,
                              void* d_out, int out_size) {
    const float* x  = (const float*)d_in[0];
    const float* w1 = (const float*)d_in[1];
    const float* b1 = (const float*)d_in[2];
    const float* w2 = (const float*)d_in[3];
    const float* b2 = (const float*)d_in[4];
    const float* wl = (const float*)d_in[5];
    const float* bl = (const float*)d_in[6];

    const int smem1 = 54544 * 4;  // 218,176 B
    const int smem2 = 48176 * 4;  // 192,704 B
    cudaFuncSetAttribute(conv1_kernel, cudaFuncAttributeMaxDynamicSharedMemorySize, smem1);
    cudaFuncSetAttribute(conv2_kernel, cudaFuncAttributeMaxDynamicSharedMemorySize, smem2);

    conv1_kernel<<<128 * 12, 576, smem1>>>(x, w1, b1);
    conv2_kernel<<<128, 432, smem2>>>(w2, b2);
    head_kernel<<<128, 128>>>(wl, bl, (float*)d_out);
}